// round 15
// baseline (speedup 1.0000x reference)
#include <cuda_runtime.h>
#include <math.h>
#include <stdint.h>

// Problem constants: x (16, 256, 1024); first = x[:4], last = x[4:]
static constexpr int CC   = 256;
static constexpr int NN   = 1024;
static constexpr int NB   = 4;      // first batches
static constexpr int NZ   = 12;     // (group-1)*b attention pairs
static constexpr int TOK  = NB * NN;

// Scratch layout (floats)
static constexpr long OFF_XQ   = 0;                        // 12*256*1024
static constexpr long OFF_XK   = OFF_XQ   + 3145728;       // 4*256*1024
static constexpr long OFF_XVT  = OFF_XK   + 1048576;       // 4*1024*256
static constexpr long OFF_E    = OFF_XVT  + 1048576;       // 12*1024*1024 (energy -> attn in place)
static constexpr long OFF_RT12 = OFF_E    + 12582912;      // 12*1024*256 (per-z attn@xv)
static constexpr long OFF_H    = OFF_RT12 + 3145728;       // 4096*256
static constexpr long OFF_H1   = OFF_H    + 1048576;       // 4096*1024
static constexpr long OFF_P4   = OFF_H1   + 4194304;       // 4*4096*256 (MLP2 split-K partials)
static constexpr long SCRATCH_TOTAL = OFF_P4 + 4194304;    // ~121.6 MB

__device__ float g_scratch[SCRATCH_TOTAL];

// ===========================================================================
// tf32 split helpers
// ===========================================================================
__device__ __forceinline__ float to_tf32(float v) {
    uint32_t u;
    asm("cvt.rna.tf32.f32 %0, %1;" : "=r"(u) : "f"(v));
    return __uint_as_float(u);
}
__device__ __forceinline__ void split_tf32(float v, float& hi, float& lo) {
    hi = to_tf32(v);
    lo = to_tf32(v - hi);
}

#define MMA_TF32(d, a, b) \
    asm("mma.sync.aligned.m16n8k8.row.col.f32.tf32.tf32.f32 " \
        "{%0,%1,%2,%3}, {%4,%5,%6,%7}, {%8,%9}, {%0,%1,%2,%3};" \
        : "+f"((d)[0]), "+f"((d)[1]), "+f"((d)[2]), "+f"((d)[3]) \
        : "r"((a)[0]), "r"((a)[1]), "r"((a)[2]), "r"((a)[3]), \
          "r"((b)[0]), "r"((b)[1]))

// ===========================================================================
// Tensor-core fp32 GEMM via tf32x3, double-buffered, 2 CTAs/SM.
// Smem layout packs hi/lo adjacent: S[k][m*2] = {hi, lo}, row stride 264
// floats -> every fragment load is one LDS.64 (hi+lo), conflict-free.
//   C[m][n] = alpha * sum_k opA[k][m]*opB[k][n]
//   AKM=true : A stored (K, M) row-major (m contiguous)
//   AKM=false: A stored (M, K) row-major -> transpose on smem store
//   (same for B/N). 128x128x16 tiles, 8 warps (2m x 4n), warp tile 64x32.
// Dynamic smem: 2 stages x BK x 264 floats for A and B = 67584 bytes.
// Requires M%128==0, N%128==0, K%32==0, leading dims %4==0.
// ===========================================================================
template<bool AKM, bool BKM>
__global__ void __launch_bounds__(256, 2)
gemm_tc(const float* __restrict__ A, const float* __restrict__ B, float* __restrict__ C,
        int K, int lda, int ldb, int ldc,
        long asb, long bsb, long csb, int aMod, int bMod,
        float alpha, const float* __restrict__ bias,
        const float* __restrict__ res, int relu)
{
    constexpr int BM = 128, BN = 128, BK = 16;
    constexpr int SROW2 = 2 * BM + 8;            // 264 floats per k-row (hi,lo interleaved)
    constexpr int PLANE = BK * SROW2;            // 4224 floats per stage per operand
    extern __shared__ float sm[];
    // SA[stage] = sm + stage*PLANE ; SB[stage] = sm + 2*PLANE + stage*PLANE
    float* SA = sm;
    float* SB = sm + 2 * PLANE;

    const int z = blockIdx.z;
    const float* Ab = A + (long)(aMod ? (z % aMod) : z) * asb;
    const float* Bb = B + (long)(bMod ? (z % bMod) : z) * bsb;
    float* Cb = C + (long)z * csb;
    const float* Rb = res ? (res + (long)z * csb) : nullptr;

    const int bm = blockIdx.y * BM;
    const int bn = blockIdx.x * BN;
    const int tid  = threadIdx.x;
    const int lane = tid & 31, warp = tid >> 5;
    const int g = lane >> 2, t = lane & 3;
    const int wm = (warp >> 2) * 64;   // 0 or 64
    const int wn = (warp & 3) * 32;    // 0,32,64,96

    float acc[4][4][4];
#pragma unroll
    for (int i = 0; i < 4; i++)
#pragma unroll
        for (int j = 0; j < 4; j++)
#pragma unroll
            for (int c = 0; c < 4; c++) acc[i][j][c] = 0.f;

    float4 ra[2], rb[2];

    auto fetch = [&](int kt) {
#pragma unroll
        for (int i = 0; i < 2; i++) {
            int v = tid + i * 256;
            if (AKM) {
                int kk = v >> 5, mv = (v & 31) << 2;
                ra[i] = *(const float4*)(Ab + (long)(kt + kk) * lda + bm + mv);
            } else {
                int mm = v >> 2, kv = (v & 3) << 2;
                ra[i] = *(const float4*)(Ab + (long)(bm + mm) * lda + kt + kv);
            }
            if (BKM) {
                int kk = v >> 5, nv = (v & 31) << 2;
                rb[i] = *(const float4*)(Bb + (long)(kt + kk) * ldb + bn + nv);
            } else {
                int nn = v >> 2, kv = (v & 3) << 2;
                rb[i] = *(const float4*)(Bb + (long)(bn + nn) * ldb + kt + kv);
            }
        }
    };

    auto store = [&](int st) {
        float* AS = SA + st * PLANE;
        float* BS = SB + st * PLANE;
#pragma unroll
        for (int i = 0; i < 2; i++) {
            int v = tid + i * 256;
            if (AKM) {
                int kk = v >> 5, mv = (v & 31) << 2;
                float4 h4, l4;
                split_tf32(ra[i].x, h4.x, l4.x); split_tf32(ra[i].y, h4.y, l4.y);
                split_tf32(ra[i].z, h4.z, l4.z); split_tf32(ra[i].w, h4.w, l4.w);
                float* p = AS + kk * SROW2 + mv * 2;
                *(float4*)(p)     = make_float4(h4.x, l4.x, h4.y, l4.y);
                *(float4*)(p + 4) = make_float4(h4.z, l4.z, h4.w, l4.w);
            } else {
                int mm = v >> 2, kv = (v & 3) << 2;
                float h, l;
                split_tf32(ra[i].x, h, l); *(float2*)(AS + (kv+0)*SROW2 + mm*2) = make_float2(h, l);
                split_tf32(ra[i].y, h, l); *(float2*)(AS + (kv+1)*SROW2 + mm*2) = make_float2(h, l);
                split_tf32(ra[i].z, h, l); *(float2*)(AS + (kv+2)*SROW2 + mm*2) = make_float2(h, l);
                split_tf32(ra[i].w, h, l); *(float2*)(AS + (kv+3)*SROW2 + mm*2) = make_float2(h, l);
            }
            if (BKM) {
                int kk = v >> 5, nv = (v & 31) << 2;
                float4 h4, l4;
                split_tf32(rb[i].x, h4.x, l4.x); split_tf32(rb[i].y, h4.y, l4.y);
                split_tf32(rb[i].z, h4.z, l4.z); split_tf32(rb[i].w, h4.w, l4.w);
                float* p = BS + kk * SROW2 + nv * 2;
                *(float4*)(p)     = make_float4(h4.x, l4.x, h4.y, l4.y);
                *(float4*)(p + 4) = make_float4(h4.z, l4.z, h4.w, l4.w);
            } else {
                int nn = v >> 2, kv = (v & 3) << 2;
                float h, l;
                split_tf32(rb[i].x, h, l); *(float2*)(BS + (kv+0)*SROW2 + nn*2) = make_float2(h, l);
                split_tf32(rb[i].y, h, l); *(float2*)(BS + (kv+1)*SROW2 + nn*2) = make_float2(h, l);
                split_tf32(rb[i].z, h, l); *(float2*)(BS + (kv+2)*SROW2 + nn*2) = make_float2(h, l);
                split_tf32(rb[i].w, h, l); *(float2*)(BS + (kv+3)*SROW2 + nn*2) = make_float2(h, l);
            }
        }
    };

    // prologue: tile 0 -> stage 0
    fetch(0);
    store(0);
    __syncthreads();

    const int ntiles = K / BK;
    for (int tt = 0; tt < ntiles; tt++) {
        if (tt + 1 < ntiles) fetch((tt + 1) * BK);  // LDG early, hidden under MMAs

        const int st = tt & 1;
        const float* AS = SA + st * PLANE;
        const float* BS = SB + st * PLANE;

#pragma unroll
        for (int ks = 0; ks < BK; ks += 8) {
            const float* Ar0 = AS + (ks + t    ) * SROW2;
            const float* Ar1 = AS + (ks + t + 4) * SROW2;
            const float* Br0 = BS + (ks + t    ) * SROW2;
            const float* Br1 = BS + (ks + t + 4) * SROW2;

            uint32_t bh[4][2], bl[4][2];
#pragma unroll
            for (int fn = 0; fn < 4; fn++) {
                int n2 = (wn + fn * 8 + g) * 2;
                float2 q0 = *(const float2*)(Br0 + n2);
                float2 q1 = *(const float2*)(Br1 + n2);
                bh[fn][0] = __float_as_uint(q0.x); bl[fn][0] = __float_as_uint(q0.y);
                bh[fn][1] = __float_as_uint(q1.x); bl[fn][1] = __float_as_uint(q1.y);
            }
#pragma unroll
            for (int fm = 0; fm < 4; fm++) {
                int m2 = (wm + fm * 16 + g) * 2;
                float2 p0 = *(const float2*)(Ar0 + m2);
                float2 p1 = *(const float2*)(Ar0 + m2 + 16);
                float2 p2 = *(const float2*)(Ar1 + m2);
                float2 p3 = *(const float2*)(Ar1 + m2 + 16);
                uint32_t ah[4], al[4];
                ah[0] = __float_as_uint(p0.x); al[0] = __float_as_uint(p0.y);
                ah[1] = __float_as_uint(p1.x); al[1] = __float_as_uint(p1.y);
                ah[2] = __float_as_uint(p2.x); al[2] = __float_as_uint(p2.y);
                ah[3] = __float_as_uint(p3.x); al[3] = __float_as_uint(p3.y);
#pragma unroll
                for (int fn = 0; fn < 4; fn++) {
                    MMA_TF32(acc[fm][fn], al, bh[fn]);   // lo*hi
                    MMA_TF32(acc[fm][fn], ah, bl[fn]);   // hi*lo
                    MMA_TF32(acc[fm][fn], ah, bh[fn]);   // hi*hi
                }
            }
        }

        if (tt + 1 < ntiles) {
            store((tt + 1) & 1);   // other stage: safe vs current compute
            __syncthreads();       // one barrier per tile
        }
    }

    // ---- epilogue ----
#pragma unroll
    for (int fm = 0; fm < 4; fm++) {
        int r0 = bm + wm + fm * 16 + g;
        int r1 = r0 + 8;
#pragma unroll
        for (int fn = 0; fn < 4; fn++) {
            int cn = bn + wn + fn * 8 + 2 * t;
            float v0 = acc[fm][fn][0] * alpha;
            float v1 = acc[fm][fn][1] * alpha;
            float v2 = acc[fm][fn][2] * alpha;
            float v3 = acc[fm][fn][3] * alpha;
            if (bias) { float b0 = bias[cn], b1x = bias[cn + 1];
                        v0 += b0; v1 += b1x; v2 += b0; v3 += b1x; }
            if (Rb)   { v0 += Rb[(long)r0 * ldc + cn];
                        v1 += Rb[(long)r0 * ldc + cn + 1];
                        v2 += Rb[(long)r1 * ldc + cn];
                        v3 += Rb[(long)r1 * ldc + cn + 1]; }
            if (relu) { v0 = fmaxf(v0, 0.f); v1 = fmaxf(v1, 0.f);
                        v2 = fmaxf(v2, 0.f); v3 = fmaxf(v3, 0.f); }
            *(float2*)(Cb + (long)r0 * ldc + cn) = make_float2(v0, v1);
            *(float2*)(Cb + (long)r1 * ldc + cn) = make_float2(v2, v3);
        }
    }
}

static constexpr size_t GEMM_TC_SMEM = (size_t)(2 * 16 * 264) * 2 * sizeof(float); // 67584

// ===========================================================================
// FFMA GEMM (small xq/xk convs, M=64 per batch)
// ===========================================================================
template<int BM, int BN, int BK, int TM, int TN, bool AKM, bool BKM, int PA, int PB>
__global__ void __launch_bounds__((BM/TM)*(BN/TN))
gemm_k(const float* __restrict__ A, const float* __restrict__ B, float* __restrict__ C,
       int K, int lda, int ldb, int ldc,
       long asb, long bsb, long csb, int aMod, int bMod,
       float alpha, const float* __restrict__ bias,
       const float* __restrict__ res, int relu)
{
    constexpr int NT = (BM/TM)*(BN/TN);
    const int z = blockIdx.z;
    const float* Ab = A + (aMod ? (long)(z % aMod) * asb : (long)z * asb);
    const float* Bb = B + (bMod ? (long)(z % bMod) * bsb : (long)z * bsb);
    float* Cb = C + (long)z * csb;
    const float* Rb = res ? (res + (long)z * csb) : nullptr;

    const int bm = blockIdx.y * BM;
    const int bn = blockIdx.x * BN;

    __shared__ float As[BK][BM + PA];
    __shared__ float Bs[BK][BN + PB];

    const int tid = threadIdx.x;
    const int tx = tid % (BN / TN);
    const int ty = tid / (BN / TN);

    float acc[TM][TN];
#pragma unroll
    for (int i = 0; i < TM; i++)
#pragma unroll
        for (int j = 0; j < TN; j++) acc[i][j] = 0.f;

    for (int kt = 0; kt < K; kt += BK) {
        if (AKM) {
#pragma unroll
            for (int v = tid; v < BK * BM / 4; v += NT) {
                int kk = v / (BM / 4), mv = v % (BM / 4);
                float4 tv = *(const float4*)(Ab + (long)(kt + kk) * lda + bm + mv * 4);
                *(float4*)&As[kk][mv * 4] = tv;
            }
        } else {
#pragma unroll
            for (int v = tid; v < BK * BM / 4; v += NT) {
                int mm = v / (BK / 4), kv = v % (BK / 4);
                float4 tv = *(const float4*)(Ab + (long)(bm + mm) * lda + kt + kv * 4);
                As[kv * 4 + 0][mm] = tv.x;
                As[kv * 4 + 1][mm] = tv.y;
                As[kv * 4 + 2][mm] = tv.z;
                As[kv * 4 + 3][mm] = tv.w;
            }
        }
        if (BKM) {
#pragma unroll
            for (int v = tid; v < BK * BN / 4; v += NT) {
                int kk = v / (BN / 4), nv = v % (BN / 4);
                float4 tv = *(const float4*)(Bb + (long)(kt + kk) * ldb + bn + nv * 4);
                *(float4*)&Bs[kk][nv * 4] = tv;
            }
        } else {
#pragma unroll
            for (int v = tid; v < BK * BN / 4; v += NT) {
                int nn = v / (BK / 4), kv = v % (BK / 4);
                float4 tv = *(const float4*)(Bb + (long)(bn + nn) * ldb + kt + kv * 4);
                Bs[kv * 4 + 0][nn] = tv.x;
                Bs[kv * 4 + 1][nn] = tv.y;
                Bs[kv * 4 + 2][nn] = tv.z;
                Bs[kv * 4 + 3][nn] = tv.w;
            }
        }
        __syncthreads();

#pragma unroll
        for (int kk = 0; kk < BK; kk++) {
            float a[TM], bfr[TN];
            float4 a0 = *(const float4*)&As[kk][ty * TM];
            float4 a1 = *(const float4*)&As[kk][ty * TM + 4];
            a[0]=a0.x; a[1]=a0.y; a[2]=a0.z; a[3]=a0.w;
            a[4]=a1.x; a[5]=a1.y; a[6]=a1.z; a[7]=a1.w;
            float4 b0 = *(const float4*)&Bs[kk][tx * TN];
            float4 b1 = *(const float4*)&Bs[kk][tx * TN + 4];
            bfr[0]=b0.x; bfr[1]=b0.y; bfr[2]=b0.z; bfr[3]=b0.w;
            bfr[4]=b1.x; bfr[5]=b1.y; bfr[6]=b1.z; bfr[7]=b1.w;
#pragma unroll
            for (int i = 0; i < TM; i++)
#pragma unroll
                for (int j = 0; j < TN; j++)
                    acc[i][j] = fmaf(a[i], bfr[j], acc[i][j]);
        }
        __syncthreads();
    }

#pragma unroll
    for (int i = 0; i < TM; i++) {
        int cm = bm + ty * TM + i;
#pragma unroll
        for (int j = 0; j < TN; j++) {
            int cn = bn + tx * TN + j;
            float v = acc[i][j] * alpha;
            if (bias) v += bias[cn];
            if (Rb)   v += Rb[(long)cm * ldc + cn];
            if (relu) v = fmaxf(v, 0.f);
            Cb[(long)cm * ldc + cn] = v;
        }
    }
}

// ===========================================================================
// In-place row softmax over last dim of E[z][n][1024]
// ===========================================================================
__global__ void softmax_inplace_k(float* __restrict__ E)
{
    const int n = blockIdx.x;
    const int z = blockIdx.y;
    float* row = E + ((long)z * NN + n) * NN;
    const int tid = threadIdx.x;  // 256

    float e[4];
#pragma unroll
    for (int k = 0; k < 4; k++) e[k] = row[tid + 256 * k];

    __shared__ float red[256];
    float m = fmaxf(fmaxf(e[0], e[1]), fmaxf(e[2], e[3]));
    red[tid] = m; __syncthreads();
    for (int s = 128; s > 0; s >>= 1) {
        if (tid < s) red[tid] = fmaxf(red[tid], red[tid + s]);
        __syncthreads();
    }
    m = red[0]; __syncthreads();

    float ssum = 0.f;
#pragma unroll
    for (int k = 0; k < 4; k++) { e[k] = expf(e[k] - m); ssum += e[k]; }
    red[tid] = ssum; __syncthreads();
    for (int s = 128; s > 0; s >>= 1) {
        if (tid < s) red[tid] += red[tid + s];
        __syncthreads();
    }
    float inv = 1.f / red[0];
#pragma unroll
    for (int k = 0; k < 4; k++) row[tid + 256 * k] = e[k] * inv;
}

// ===========================================================================
// LN1 (fused 3-way mean of Rt12 + residual): h[t][c] = LN_c(x[b][c][n] + xr)
// ===========================================================================
__global__ void ln1_k(const float* __restrict__ x, const float* __restrict__ Rt12,
                      const float* __restrict__ gam, const float* __restrict__ bet,
                      float* __restrict__ h)
{
    const int t = blockIdx.x;
    const int b = t >> 10, n = t & 1023;
    const int c = threadIdx.x;
    long base = ((long)(3 * b) * NN + n) * CC + c;
    float r = Rt12[base] + Rt12[base + (long)NN * CC] + Rt12[base + 2L * NN * CC];
    float v = x[((long)b * CC + c) * NN + n] + r * (1.f / 48.f);

    __shared__ float red[256];
    red[c] = v; __syncthreads();
    for (int s = 128; s > 0; s >>= 1) { if (c < s) red[c] += red[c + s]; __syncthreads(); }
    float mu = red[0] * (1.f / CC); __syncthreads();
    float d = v - mu;
    red[c] = d * d; __syncthreads();
    for (int s = 128; s > 0; s >>= 1) { if (c < s) red[c] += red[c + s]; __syncthreads(); }
    float var = red[0] * (1.f / CC);
    h[(long)t * CC + c] = d * rsqrtf(var + 1e-6f) * gam[c] + bet[c];
}

// ===========================================================================
// LN2 (fused MLP2 split-K reduce + bias + residual) + relu + transposed write
// ===========================================================================
__global__ void ln2_out_k(const float* __restrict__ P4, const float* __restrict__ h,
                          const float* __restrict__ b2,
                          const float* __restrict__ gam, const float* __restrict__ bet,
                          float* __restrict__ out)
{
    const int t = blockIdx.x;
    const int b = t >> 10, n = t & 1023;
    const int c = threadIdx.x;
    long idx = (long)t * CC + c;
    float v = h[idx] + b2[c];
#pragma unroll
    for (int z = 0; z < 4; z++) v += P4[(long)z * TOK * CC + idx];

    __shared__ float red[256];
    red[c] = v; __syncthreads();
    for (int s = 128; s > 0; s >>= 1) { if (c < s) red[c] += red[c + s]; __syncthreads(); }
    float mu = red[0] * (1.f / CC); __syncthreads();
    float d = v - mu;
    red[c] = d * d; __syncthreads();
    for (int s = 128; s > 0; s >>= 1) { if (c < s) red[c] += red[c + s]; __syncthreads(); }
    float var = red[0] * (1.f / CC);
    float hv = d * rsqrtf(var + 1e-6f) * gam[c] + bet[c];
    out[((long)b * CC + c) * NN + n] = fmaxf(hv, 0.f);
}

// ===========================================================================
extern "C" void kernel_launch(void* const* d_in, const int* in_sizes, int n_in,
                              void* d_out, int out_size)
{
    (void)in_sizes; (void)n_in; (void)out_size;
    const float* x     = (const float*)d_in[0];
    const float* Wq    = (const float*)d_in[1];
    const float* Wk    = (const float*)d_in[2];
    const float* Wv    = (const float*)d_in[3];
    const float* bv    = (const float*)d_in[4];
    const float* ln1_g = (const float*)d_in[5];
    const float* ln1_b = (const float*)d_in[6];
    const float* W1    = (const float*)d_in[7];
    const float* b1    = (const float*)d_in[8];
    const float* W2    = (const float*)d_in[9];
    const float* b2    = (const float*)d_in[10];
    const float* ln2_g = (const float*)d_in[11];
    const float* ln2_b = (const float*)d_in[12];
    float* out = (float*)d_out;

    // raise dynamic smem cap for the TC kernels (host-side config; idempotent)
    cudaFuncSetAttribute(gemm_tc<true,true>,   cudaFuncAttributeMaxDynamicSharedMemorySize, (int)GEMM_TC_SMEM);
    cudaFuncSetAttribute(gemm_tc<true,false>,  cudaFuncAttributeMaxDynamicSharedMemorySize, (int)GEMM_TC_SMEM);
    cudaFuncSetAttribute(gemm_tc<false,false>, cudaFuncAttributeMaxDynamicSharedMemorySize, (int)GEMM_TC_SMEM);

    float* S = nullptr;
    cudaGetSymbolAddress((void**)&S, g_scratch);
    float* xq   = S + OFF_XQ;
    float* xk   = S + OFF_XK;
    float* xvT  = S + OFF_XVT;
    float* E    = S + OFF_E;
    float* Rt12 = S + OFF_RT12;
    float* h    = S + OFF_H;
    float* H1   = S + OFF_H1;
    float* P4   = S + OFF_P4;

    const float* xlast = x + (long)NB * CC * NN;

    // out[4:] = last (unchanged)
    cudaMemcpyAsync(out + (long)NB * CC * NN, xlast,
                    (size_t)12 * CC * NN * sizeof(float),
                    cudaMemcpyDeviceToDevice, 0);

    // xq[z=(B,s)][o][n] = Wq[s] @ last[B, s*64.., :]  (48 batches 64x1024x64, FFMA)
    gemm_k<64,128,16,8,8,false,true,4,0><<<dim3(8,1,48),128>>>(
        Wq, xlast, xq, 64, 64, NN, NN,
        (long)64*64, (long)64*NN, (long)64*NN, 4, 0,
        1.f, nullptr, nullptr, 0);

    // xk: 16 batches 64x1024x64 over first (FFMA)
    gemm_k<64,128,16,8,8,false,true,4,0><<<dim3(8,1,16),128>>>(
        Wk, x, xk, 64, 64, NN, NN,
        (long)64*64, (long)64*NN, (long)64*NN, 4, 0,
        1.f, nullptr, nullptr, 0);

    // xvT[b][n][c] = (Wv @ x[b])^T + bv   (4 batches 1024x256x256, TC)
    gemm_tc<true,false><<<dim3(2,8,4),256,GEMM_TC_SMEM>>>(
        x, Wv, xvT, CC, NN, CC, CC,
        (long)CC*NN, 0L, (long)NN*CC, 0, 0,
        1.f, bv, nullptr, 0);

    // energy: E[z][n][m] = sum_ch xq[z][ch][n] * xk[z%4][ch][m]  (12 x 1024x1024x256, TC)
    gemm_tc<true,true><<<dim3(8,8,12),256,GEMM_TC_SMEM>>>(
        xq, xk, E, CC, NN, NN, NN,
        (long)CC*NN, (long)CC*NN, (long)NN*NN, 0, 4,
        1.f, nullptr, nullptr, 0);

    // softmax rows in place
    softmax_inplace_k<<<dim3(NN, NZ), 256>>>(E);

    // per-z apply: Rt12[z][m][c] = sum_k attn[z][k][m] * xvT[z%4][k][c]  (12 x 1024x256x1024, TC)
    gemm_tc<true,true><<<dim3(2,8,12),256,GEMM_TC_SMEM>>>(
        E, xvT, Rt12, NN, NN, CC, CC,
        (long)NN*NN, (long)NN*CC, (long)NN*CC, 0, 4,
        1.f, nullptr, nullptr, 0);

    // LN1 (3-way mean * 1/48 + residual fused)
    ln1_k<<<TOK, 256>>>(x, Rt12, ln1_g, ln1_b, h);

    // MLP1: H1 = relu(h @ W1^T + b1)   (4096x1024x256, TC)
    gemm_tc<false,false><<<dim3(8,32,1),256,GEMM_TC_SMEM>>>(
        h, W1, H1, CC, CC, CC, 4*CC,
        0L, 0L, 0L, 0, 0,
        1.f, b1, nullptr, 1);

    // MLP2 split-K (4 chunks of K=256): P4[z] = H1[:, z*256:+256] @ W2[:, z*256:+256]^T
    gemm_tc<false,false><<<dim3(2,32,4),256,GEMM_TC_SMEM>>>(
        H1, W2, P4, CC, 4*CC, 4*CC, CC,
        256L, 256L, (long)TOK*CC, 0, 0,
        1.f, nullptr, nullptr, 0);

    // LN2 (split-K reduce + b2 + residual h fused) + relu + transpose into out[:4]
    ln2_out_k<<<TOK, 256>>>(P4, h, b2, ln2_g, ln2_b, out);
}

// round 16
// speedup vs baseline: 1.1700x; 1.1700x over previous
#include <cuda_runtime.h>
#include <math.h>
#include <stdint.h>

// Problem constants: x (16, 256, 1024); first = x[:4], last = x[4:]
static constexpr int CC   = 256;
static constexpr int NN   = 1024;
static constexpr int NB   = 4;      // first batches
static constexpr int NZ   = 12;     // (group-1)*b attention pairs
static constexpr int TOK  = NB * NN;

// Scratch layout (floats)
static constexpr long OFF_XQH  = 0;                        // 12*256*1024
static constexpr long OFF_XQL  = OFF_XQH + 3145728;
static constexpr long OFF_XKH  = OFF_XQL + 3145728;        // 4*256*1024
static constexpr long OFF_XKL  = OFF_XKH + 1048576;
static constexpr long OFF_XVH  = OFF_XKL + 1048576;        // 4*1024*256
static constexpr long OFF_XVL  = OFF_XVH + 1048576;
static constexpr long OFF_E    = OFF_XVL + 1048576;        // 12*1024*1024 raw energy
static constexpr long OFF_ATH  = OFF_E   + 12582912;       // attn hi
static constexpr long OFF_ATL  = OFF_ATH + 12582912;       // attn lo
static constexpr long OFF_RT12 = OFF_ATL + 12582912;       // 12*1024*256
static constexpr long OFF_H    = OFF_RT12 + 3145728;       // 4096*256
static constexpr long OFF_H1   = OFF_H    + 1048576;       // 4096*1024
static constexpr long OFF_P4   = OFF_H1   + 4194304;       // 4*4096*256
static constexpr long SCRATCH_TOTAL = OFF_P4 + 4194304;    // ~243 MB

__device__ float g_scratch[SCRATCH_TOTAL];

// ===========================================================================
// tf32 split helpers + cp.async
// ===========================================================================
__device__ __forceinline__ float to_tf32(float v) {
    uint32_t u;
    asm("cvt.rna.tf32.f32 %0, %1;" : "=r"(u) : "f"(v));
    return __uint_as_float(u);
}
__device__ __forceinline__ void split_tf32(float v, float& hi, float& lo) {
    hi = to_tf32(v);
    lo = to_tf32(v - hi);
}
__device__ __forceinline__ void cp_async16(uint32_t s, const void* g) {
    asm volatile("cp.async.cg.shared.global [%0], [%1], 16;" :: "r"(s), "l"(g));
}
#define CP_COMMIT() asm volatile("cp.async.commit_group;")
#define CP_WAIT0()  asm volatile("cp.async.wait_group 0;")

#define MMA_TF32(d, a, b) \
    asm("mma.sync.aligned.m16n8k8.row.col.f32.tf32.tf32.f32 " \
        "{%0,%1,%2,%3}, {%4,%5,%6,%7}, {%8,%9}, {%0,%1,%2,%3};" \
        : "+f"((d)[0]), "+f"((d)[1]), "+f"((d)[2]), "+f"((d)[3]) \
        : "r"((a)[0]), "r"((a)[1]), "r"((a)[2]), "r"((a)[3]), \
          "r"((b)[0]), "r"((b)[1]))

// ===========================================================================
// gemm_tc2: pre-split tf32x3 GEMM, both operands K-major, cp.async pipeline.
//   C[m][n] = alpha * sum_k A[k][m]*B[k][n], A/B given as hi/lo planes.
// 128x128x16 tiles, 8 warps (2m x 4n), 2 stages, 2 CTAs/SM.
// Dynamic smem: 2 stages x 4 planes x 16 x 136 floats = 69632 bytes.
// ===========================================================================
__global__ void __launch_bounds__(256, 2)
gemm_tc2(const float* __restrict__ Ahi, const float* __restrict__ Alo,
         const float* __restrict__ Bhi, const float* __restrict__ Blo,
         float* __restrict__ C, int K, int lda, int ldb, int ldc,
         long asb, long bsb, long csb, int aMod, int bMod, float alpha)
{
    constexpr int BM = 128, BN = 128, BK = 16;
    constexpr int SROW = BM + 8;          // 136
    constexpr int PLANE = BK * SROW;      // 2176 floats
    extern __shared__ float sm[];

    const int z = blockIdx.z;
    const long aoff = (long)(aMod ? (z % aMod) : z) * asb;
    const long boff = (long)(bMod ? (z % bMod) : z) * bsb;
    const float* pAh = Ahi + aoff; const float* pAl = Alo + aoff;
    const float* pBh = Bhi + boff; const float* pBl = Blo + boff;
    float* Cb = C + (long)z * csb;

    const int bm = blockIdx.y * BM;
    const int bn = blockIdx.x * BN;
    const int tid  = threadIdx.x;
    const int lane = tid & 31, warp = tid >> 5;
    const int g = lane >> 2, t = lane & 3;
    const int wm = (warp >> 2) * 64;
    const int wn = (warp & 3) * 32;

    float acc[4][4][4];
#pragma unroll
    for (int i = 0; i < 4; i++)
#pragma unroll
        for (int j = 0; j < 4; j++)
#pragma unroll
            for (int c = 0; c < 4; c++) acc[i][j][c] = 0.f;

    const uint32_t smbase = (uint32_t)__cvta_generic_to_shared(sm);

    auto issue = [&](int tt) {
        const int st = tt & 1;
        const int kt = tt * BK;
        const uint32_t base = smbase + (uint32_t)(st * 4 * PLANE) * 4u;
#pragma unroll
        for (int i = 0; i < 2; i++) {
            int v = tid + i * 256;                 // 512 chunks of 16B per plane
            int kk = v >> 5, c4 = (v & 31) << 2;
            uint32_t soff = (uint32_t)(kk * SROW + c4) * 4u;
            long ga = (long)(kt + kk) * lda + bm + c4;
            long gb = (long)(kt + kk) * ldb + bn + c4;
            cp_async16(base + 0u * PLANE * 4u + soff, pAh + ga);
            cp_async16(base + 1u * PLANE * 4u + soff, pAl + ga);
            cp_async16(base + 2u * PLANE * 4u + soff, pBh + gb);
            cp_async16(base + 3u * PLANE * 4u + soff, pBl + gb);
        }
        CP_COMMIT();
    };

    issue(0);
    const int ntiles = K / BK;
    for (int tt = 0; tt < ntiles; tt++) {
        CP_WAIT0();
        __syncthreads();           // all warps done with compute(tt-1), stage tt data visible
        if (tt + 1 < ntiles) issue(tt + 1);   // into the other stage, overlaps compute(tt)

        const int st = tt & 1;
        const float* AH = sm + st * 4 * PLANE;
        const float* AL = AH + PLANE;
        const float* BH = AL + PLANE;
        const float* BL = BH + PLANE;

#pragma unroll
        for (int ks = 0; ks < BK; ks += 8) {
            uint32_t bh[4][2], bl[4][2];
#pragma unroll
            for (int fn = 0; fn < 4; fn++) {
                int n = wn + fn * 8 + g;
                bh[fn][0] = __float_as_uint(BH[(ks + t    ) * SROW + n]);
                bh[fn][1] = __float_as_uint(BH[(ks + t + 4) * SROW + n]);
                bl[fn][0] = __float_as_uint(BL[(ks + t    ) * SROW + n]);
                bl[fn][1] = __float_as_uint(BL[(ks + t + 4) * SROW + n]);
            }
#pragma unroll
            for (int fm = 0; fm < 4; fm++) {
                int m = wm + fm * 16 + g;
                uint32_t ah[4], al[4];
                ah[0] = __float_as_uint(AH[(ks + t    ) * SROW + m]);
                ah[1] = __float_as_uint(AH[(ks + t    ) * SROW + m + 8]);
                ah[2] = __float_as_uint(AH[(ks + t + 4) * SROW + m]);
                ah[3] = __float_as_uint(AH[(ks + t + 4) * SROW + m + 8]);
                al[0] = __float_as_uint(AL[(ks + t    ) * SROW + m]);
                al[1] = __float_as_uint(AL[(ks + t    ) * SROW + m + 8]);
                al[2] = __float_as_uint(AL[(ks + t + 4) * SROW + m]);
                al[3] = __float_as_uint(AL[(ks + t + 4) * SROW + m + 8]);
#pragma unroll
                for (int fn = 0; fn < 4; fn++) {
                    MMA_TF32(acc[fm][fn], al, bh[fn]);
                    MMA_TF32(acc[fm][fn], ah, bl[fn]);
                    MMA_TF32(acc[fm][fn], ah, bh[fn]);
                }
            }
        }
    }

#pragma unroll
    for (int fm = 0; fm < 4; fm++) {
        int r0 = bm + wm + fm * 16 + g;
        int r1 = r0 + 8;
#pragma unroll
        for (int fn = 0; fn < 4; fn++) {
            int cn = bn + wn + fn * 8 + 2 * t;
            *(float2*)(Cb + (long)r0 * ldc + cn) =
                make_float2(acc[fm][fn][0] * alpha, acc[fm][fn][1] * alpha);
            *(float2*)(Cb + (long)r1 * ldc + cn) =
                make_float2(acc[fm][fn][2] * alpha, acc[fm][fn][3] * alpha);
        }
    }
}

static constexpr size_t GEMM_TC2_SMEM = (size_t)(2 * 4 * 16 * 136) * sizeof(float); // 69632

// ===========================================================================
// gemm_tc: R14 tf32x3 GEMM (split-on-store), double-buffered, 2 CTAs/SM.
// Optional split output (Clo != nullptr): writes hi into C, lo into Clo.
// ===========================================================================
template<bool AKM, bool BKM>
__global__ void __launch_bounds__(256, 2)
gemm_tc(const float* __restrict__ A, const float* __restrict__ B, float* __restrict__ C,
        int K, int lda, int ldb, int ldc,
        long asb, long bsb, long csb, int aMod, int bMod,
        float alpha, const float* __restrict__ bias,
        const float* __restrict__ res, int relu, float* __restrict__ Clo)
{
    constexpr int BM = 128, BN = 128, BK = 16;
    constexpr int SROW = BM + 8;
    extern __shared__ float sm[];
    float* SA = sm;
    float* SB = sm + 2 * 2 * BK * SROW;

    const int z = blockIdx.z;
    const float* Ab = A + (long)(aMod ? (z % aMod) : z) * asb;
    const float* Bb = B + (long)(bMod ? (z % bMod) : z) * bsb;
    float* Cb = C + (long)z * csb;
    float* CbL = Clo ? (Clo + (long)z * csb) : nullptr;
    const float* Rb = res ? (res + (long)z * csb) : nullptr;

    const int bm = blockIdx.y * BM;
    const int bn = blockIdx.x * BN;
    const int tid  = threadIdx.x;
    const int lane = tid & 31, warp = tid >> 5;
    const int g = lane >> 2, t = lane & 3;
    const int wm = (warp >> 2) * 64;
    const int wn = (warp & 3) * 32;

    float acc[4][4][4];
#pragma unroll
    for (int i = 0; i < 4; i++)
#pragma unroll
        for (int j = 0; j < 4; j++)
#pragma unroll
            for (int c = 0; c < 4; c++) acc[i][j][c] = 0.f;

    float4 ra[2], rb[2];

    auto fetch = [&](int kt) {
#pragma unroll
        for (int i = 0; i < 2; i++) {
            int v = tid + i * 256;
            if (AKM) {
                int kk = v >> 5, mv = (v & 31) << 2;
                ra[i] = *(const float4*)(Ab + (long)(kt + kk) * lda + bm + mv);
            } else {
                int mm = v >> 2, kv = (v & 3) << 2;
                ra[i] = *(const float4*)(Ab + (long)(bm + mm) * lda + kt + kv);
            }
            if (BKM) {
                int kk = v >> 5, nv = (v & 31) << 2;
                rb[i] = *(const float4*)(Bb + (long)(kt + kk) * ldb + bn + nv);
            } else {
                int nn = v >> 2, kv = (v & 3) << 2;
                rb[i] = *(const float4*)(Bb + (long)(bn + nn) * ldb + kt + kv);
            }
        }
    };

    auto store = [&](int st) {
        float* AH = SA + (st * 2 + 0) * BK * SROW;
        float* AL = SA + (st * 2 + 1) * BK * SROW;
        float* BH = SB + (st * 2 + 0) * BK * SROW;
        float* BL = SB + (st * 2 + 1) * BK * SROW;
#pragma unroll
        for (int i = 0; i < 2; i++) {
            int v = tid + i * 256;
            if (AKM) {
                int kk = v >> 5, mv = (v & 31) << 2;
                float4 h4, l4;
                split_tf32(ra[i].x, h4.x, l4.x); split_tf32(ra[i].y, h4.y, l4.y);
                split_tf32(ra[i].z, h4.z, l4.z); split_tf32(ra[i].w, h4.w, l4.w);
                *(float4*)(AH + kk * SROW + mv) = h4;
                *(float4*)(AL + kk * SROW + mv) = l4;
            } else {
                int mm = v >> 2, kv = (v & 3) << 2;
                float h, l;
                split_tf32(ra[i].x, h, l); AH[(kv+0)*SROW+mm] = h; AL[(kv+0)*SROW+mm] = l;
                split_tf32(ra[i].y, h, l); AH[(kv+1)*SROW+mm] = h; AL[(kv+1)*SROW+mm] = l;
                split_tf32(ra[i].z, h, l); AH[(kv+2)*SROW+mm] = h; AL[(kv+2)*SROW+mm] = l;
                split_tf32(ra[i].w, h, l); AH[(kv+3)*SROW+mm] = h; AL[(kv+3)*SROW+mm] = l;
            }
            if (BKM) {
                int kk = v >> 5, nv = (v & 31) << 2;
                float4 h4, l4;
                split_tf32(rb[i].x, h4.x, l4.x); split_tf32(rb[i].y, h4.y, l4.y);
                split_tf32(rb[i].z, h4.z, l4.z); split_tf32(rb[i].w, h4.w, l4.w);
                *(float4*)(BH + kk * SROW + nv) = h4;
                *(float4*)(BL + kk * SROW + nv) = l4;
            } else {
                int nn = v >> 2, kv = (v & 3) << 2;
                float h, l;
                split_tf32(rb[i].x, h, l); BH[(kv+0)*SROW+nn] = h; BL[(kv+0)*SROW+nn] = l;
                split_tf32(rb[i].y, h, l); BH[(kv+1)*SROW+nn] = h; BL[(kv+1)*SROW+nn] = l;
                split_tf32(rb[i].z, h, l); BH[(kv+2)*SROW+nn] = h; BL[(kv+2)*SROW+nn] = l;
                split_tf32(rb[i].w, h, l); BH[(kv+3)*SROW+nn] = h; BL[(kv+3)*SROW+nn] = l;
            }
        }
    };

    fetch(0);
    store(0);
    __syncthreads();

    const int ntiles = K / BK;
    for (int tt = 0; tt < ntiles; tt++) {
        if (tt + 1 < ntiles) fetch((tt + 1) * BK);

        const int st = tt & 1;
        const float* AH = SA + (st * 2 + 0) * BK * SROW;
        const float* AL = SA + (st * 2 + 1) * BK * SROW;
        const float* BH = SB + (st * 2 + 0) * BK * SROW;
        const float* BL = SB + (st * 2 + 1) * BK * SROW;

#pragma unroll
        for (int ks = 0; ks < BK; ks += 8) {
            uint32_t bh[4][2], bl[4][2];
#pragma unroll
            for (int fn = 0; fn < 4; fn++) {
                int n = wn + fn * 8 + g;
                bh[fn][0] = __float_as_uint(BH[(ks + t    ) * SROW + n]);
                bh[fn][1] = __float_as_uint(BH[(ks + t + 4) * SROW + n]);
                bl[fn][0] = __float_as_uint(BL[(ks + t    ) * SROW + n]);
                bl[fn][1] = __float_as_uint(BL[(ks + t + 4) * SROW + n]);
            }
#pragma unroll
            for (int fm = 0; fm < 4; fm++) {
                int m = wm + fm * 16 + g;
                uint32_t ah[4], al[4];
                ah[0] = __float_as_uint(AH[(ks + t    ) * SROW + m]);
                ah[1] = __float_as_uint(AH[(ks + t    ) * SROW + m + 8]);
                ah[2] = __float_as_uint(AH[(ks + t + 4) * SROW + m]);
                ah[3] = __float_as_uint(AH[(ks + t + 4) * SROW + m + 8]);
                al[0] = __float_as_uint(AL[(ks + t    ) * SROW + m]);
                al[1] = __float_as_uint(AL[(ks + t    ) * SROW + m + 8]);
                al[2] = __float_as_uint(AL[(ks + t + 4) * SROW + m]);
                al[3] = __float_as_uint(AL[(ks + t + 4) * SROW + m + 8]);
#pragma unroll
                for (int fn = 0; fn < 4; fn++) {
                    MMA_TF32(acc[fm][fn], al, bh[fn]);
                    MMA_TF32(acc[fm][fn], ah, bl[fn]);
                    MMA_TF32(acc[fm][fn], ah, bh[fn]);
                }
            }
        }

        if (tt + 1 < ntiles) {
            store((tt + 1) & 1);
            __syncthreads();
        }
    }

#pragma unroll
    for (int fm = 0; fm < 4; fm++) {
        int r0 = bm + wm + fm * 16 + g;
        int r1 = r0 + 8;
#pragma unroll
        for (int fn = 0; fn < 4; fn++) {
            int cn = bn + wn + fn * 8 + 2 * t;
            float v0 = acc[fm][fn][0] * alpha;
            float v1 = acc[fm][fn][1] * alpha;
            float v2 = acc[fm][fn][2] * alpha;
            float v3 = acc[fm][fn][3] * alpha;
            if (bias) { float b0 = bias[cn], b1x = bias[cn + 1];
                        v0 += b0; v1 += b1x; v2 += b0; v3 += b1x; }
            if (Rb)   { v0 += Rb[(long)r0 * ldc + cn];
                        v1 += Rb[(long)r0 * ldc + cn + 1];
                        v2 += Rb[(long)r1 * ldc + cn];
                        v3 += Rb[(long)r1 * ldc + cn + 1]; }
            if (relu) { v0 = fmaxf(v0, 0.f); v1 = fmaxf(v1, 0.f);
                        v2 = fmaxf(v2, 0.f); v3 = fmaxf(v3, 0.f); }
            if (CbL) {
                float h, l;
                split_tf32(v0, h, l); Cb[(long)r0*ldc+cn]   = h; CbL[(long)r0*ldc+cn]   = l;
                split_tf32(v1, h, l); Cb[(long)r0*ldc+cn+1] = h; CbL[(long)r0*ldc+cn+1] = l;
                split_tf32(v2, h, l); Cb[(long)r1*ldc+cn]   = h; CbL[(long)r1*ldc+cn]   = l;
                split_tf32(v3, h, l); Cb[(long)r1*ldc+cn+1] = h; CbL[(long)r1*ldc+cn+1] = l;
            } else {
                *(float2*)(Cb + (long)r0 * ldc + cn) = make_float2(v0, v1);
                *(float2*)(Cb + (long)r1 * ldc + cn) = make_float2(v2, v3);
            }
        }
    }
}

static constexpr size_t GEMM_TC_SMEM = (size_t)(2 * 2 * 16 * 136) * 2 * sizeof(float); // 69632

// ===========================================================================
// FFMA GEMM (small xq/xk convs); optional split output via Clo.
// ===========================================================================
template<int BM, int BN, int BK, int TM, int TN, bool AKM, bool BKM, int PA, int PB>
__global__ void __launch_bounds__((BM/TM)*(BN/TN))
gemm_k(const float* __restrict__ A, const float* __restrict__ B, float* __restrict__ C,
       int K, int lda, int ldb, int ldc,
       long asb, long bsb, long csb, int aMod, int bMod,
       float alpha, float* __restrict__ Clo)
{
    constexpr int NT = (BM/TM)*(BN/TN);
    const int z = blockIdx.z;
    const float* Ab = A + (aMod ? (long)(z % aMod) * asb : (long)z * asb);
    const float* Bb = B + (bMod ? (long)(z % bMod) * bsb : (long)z * bsb);
    float* Cb = C + (long)z * csb;
    float* CbL = Clo ? (Clo + (long)z * csb) : nullptr;

    const int bm = blockIdx.y * BM;
    const int bn = blockIdx.x * BN;

    __shared__ float As[BK][BM + PA];
    __shared__ float Bs[BK][BN + PB];

    const int tid = threadIdx.x;
    const int tx = tid % (BN / TN);
    const int ty = tid / (BN / TN);

    float acc[TM][TN];
#pragma unroll
    for (int i = 0; i < TM; i++)
#pragma unroll
        for (int j = 0; j < TN; j++) acc[i][j] = 0.f;

    for (int kt = 0; kt < K; kt += BK) {
        if (AKM) {
#pragma unroll
            for (int v = tid; v < BK * BM / 4; v += NT) {
                int kk = v / (BM / 4), mv = v % (BM / 4);
                float4 tv = *(const float4*)(Ab + (long)(kt + kk) * lda + bm + mv * 4);
                *(float4*)&As[kk][mv * 4] = tv;
            }
        } else {
#pragma unroll
            for (int v = tid; v < BK * BM / 4; v += NT) {
                int mm = v / (BK / 4), kv = v % (BK / 4);
                float4 tv = *(const float4*)(Ab + (long)(bm + mm) * lda + kt + kv * 4);
                As[kv * 4 + 0][mm] = tv.x;
                As[kv * 4 + 1][mm] = tv.y;
                As[kv * 4 + 2][mm] = tv.z;
                As[kv * 4 + 3][mm] = tv.w;
            }
        }
        if (BKM) {
#pragma unroll
            for (int v = tid; v < BK * BN / 4; v += NT) {
                int kk = v / (BN / 4), nv = v % (BN / 4);
                float4 tv = *(const float4*)(Bb + (long)(kt + kk) * ldb + bn + nv * 4);
                *(float4*)&Bs[kk][nv * 4] = tv;
            }
        } else {
#pragma unroll
            for (int v = tid; v < BK * BN / 4; v += NT) {
                int nn = v / (BK / 4), kv = v % (BK / 4);
                float4 tv = *(const float4*)(Bb + (long)(bn + nn) * ldb + kt + kv * 4);
                Bs[kv * 4 + 0][nn] = tv.x;
                Bs[kv * 4 + 1][nn] = tv.y;
                Bs[kv * 4 + 2][nn] = tv.z;
                Bs[kv * 4 + 3][nn] = tv.w;
            }
        }
        __syncthreads();

#pragma unroll
        for (int kk = 0; kk < BK; kk++) {
            float a[TM], bfr[TN];
            float4 a0 = *(const float4*)&As[kk][ty * TM];
            float4 a1 = *(const float4*)&As[kk][ty * TM + 4];
            a[0]=a0.x; a[1]=a0.y; a[2]=a0.z; a[3]=a0.w;
            a[4]=a1.x; a[5]=a1.y; a[6]=a1.z; a[7]=a1.w;
            float4 b0 = *(const float4*)&Bs[kk][tx * TN];
            float4 b1 = *(const float4*)&Bs[kk][tx * TN + 4];
            bfr[0]=b0.x; bfr[1]=b0.y; bfr[2]=b0.z; bfr[3]=b0.w;
            bfr[4]=b1.x; bfr[5]=b1.y; bfr[6]=b1.z; bfr[7]=b1.w;
#pragma unroll
            for (int i = 0; i < TM; i++)
#pragma unroll
                for (int j = 0; j < TN; j++)
                    acc[i][j] = fmaf(a[i], bfr[j], acc[i][j]);
        }
        __syncthreads();
    }

#pragma unroll
    for (int i = 0; i < TM; i++) {
        int cm = bm + ty * TM + i;
#pragma unroll
        for (int j = 0; j < TN; j++) {
            int cn = bn + tx * TN + j;
            float v = acc[i][j] * alpha;
            if (CbL) {
                float h, l;
                split_tf32(v, h, l);
                Cb[(long)cm * ldc + cn]  = h;
                CbL[(long)cm * ldc + cn] = l;
            } else {
                Cb[(long)cm * ldc + cn] = v;
            }
        }
    }
}

// ===========================================================================
// Softmax over last dim of E[z][n][1024]; writes split attn hi/lo
// ===========================================================================
__global__ void softmax_split_k(const float* __restrict__ E,
                                float* __restrict__ Ah, float* __restrict__ Al)
{
    const int n = blockIdx.x;
    const int z = blockIdx.y;
    const long roff = ((long)z * NN + n) * NN;
    const float* row = E + roff;
    const int tid = threadIdx.x;  // 256

    float e[4];
#pragma unroll
    for (int k = 0; k < 4; k++) e[k] = row[tid + 256 * k];

    __shared__ float red[256];
    float m = fmaxf(fmaxf(e[0], e[1]), fmaxf(e[2], e[3]));
    red[tid] = m; __syncthreads();
    for (int s = 128; s > 0; s >>= 1) {
        if (tid < s) red[tid] = fmaxf(red[tid], red[tid + s]);
        __syncthreads();
    }
    m = red[0]; __syncthreads();

    float ssum = 0.f;
#pragma unroll
    for (int k = 0; k < 4; k++) { e[k] = expf(e[k] - m); ssum += e[k]; }
    red[tid] = ssum; __syncthreads();
    for (int s = 128; s > 0; s >>= 1) {
        if (tid < s) red[tid] += red[tid + s];
        __syncthreads();
    }
    float inv = 1.f / red[0];
#pragma unroll
    for (int k = 0; k < 4; k++) {
        float v = e[k] * inv;
        float hi, lo;
        split_tf32(v, hi, lo);
        Ah[roff + tid + 256 * k] = hi;
        Al[roff + tid + 256 * k] = lo;
    }
}

// ===========================================================================
// LN1 (fused 3-way mean of Rt12 + residual): h[t][c] = LN_c(x[b][c][n] + xr)
// ===========================================================================
__global__ void ln1_k(const float* __restrict__ x, const float* __restrict__ Rt12,
                      const float* __restrict__ gam, const float* __restrict__ bet,
                      float* __restrict__ h)
{
    const int t = blockIdx.x;
    const int b = t >> 10, n = t & 1023;
    const int c = threadIdx.x;
    long base = ((long)(3 * b) * NN + n) * CC + c;
    float r = Rt12[base] + Rt12[base + (long)NN * CC] + Rt12[base + 2L * NN * CC];
    float v = x[((long)b * CC + c) * NN + n] + r * (1.f / 48.f);

    __shared__ float red[256];
    red[c] = v; __syncthreads();
    for (int s = 128; s > 0; s >>= 1) { if (c < s) red[c] += red[c + s]; __syncthreads(); }
    float mu = red[0] * (1.f / CC); __syncthreads();
    float d = v - mu;
    red[c] = d * d; __syncthreads();
    for (int s = 128; s > 0; s >>= 1) { if (c < s) red[c] += red[c + s]; __syncthreads(); }
    float var = red[0] * (1.f / CC);
    h[(long)t * CC + c] = d * rsqrtf(var + 1e-6f) * gam[c] + bet[c];
}

// ===========================================================================
// LN2 (fused MLP2 split-K reduce + bias + residual) + relu + transposed write
// ===========================================================================
__global__ void ln2_out_k(const float* __restrict__ P4, const float* __restrict__ h,
                          const float* __restrict__ b2,
                          const float* __restrict__ gam, const float* __restrict__ bet,
                          float* __restrict__ out)
{
    const int t = blockIdx.x;
    const int b = t >> 10, n = t & 1023;
    const int c = threadIdx.x;
    long idx = (long)t * CC + c;
    float v = h[idx] + b2[c];
#pragma unroll
    for (int z = 0; z < 4; z++) v += P4[(long)z * TOK * CC + idx];

    __shared__ float red[256];
    red[c] = v; __syncthreads();
    for (int s = 128; s > 0; s >>= 1) { if (c < s) red[c] += red[c + s]; __syncthreads(); }
    float mu = red[0] * (1.f / CC); __syncthreads();
    float d = v - mu;
    red[c] = d * d; __syncthreads();
    for (int s = 128; s > 0; s >>= 1) { if (c < s) red[c] += red[c + s]; __syncthreads(); }
    float var = red[0] * (1.f / CC);
    float hv = d * rsqrtf(var + 1e-6f) * gam[c] + bet[c];
    out[((long)b * CC + c) * NN + n] = fmaxf(hv, 0.f);
}

// ===========================================================================
extern "C" void kernel_launch(void* const* d_in, const int* in_sizes, int n_in,
                              void* d_out, int out_size)
{
    (void)in_sizes; (void)n_in; (void)out_size;
    const float* x     = (const float*)d_in[0];
    const float* Wq    = (const float*)d_in[1];
    const float* Wk    = (const float*)d_in[2];
    const float* Wv    = (const float*)d_in[3];
    const float* bv    = (const float*)d_in[4];
    const float* ln1_g = (const float*)d_in[5];
    const float* ln1_b = (const float*)d_in[6];
    const float* W1    = (const float*)d_in[7];
    const float* b1    = (const float*)d_in[8];
    const float* W2    = (const float*)d_in[9];
    const float* b2    = (const float*)d_in[10];
    const float* ln2_g = (const float*)d_in[11];
    const float* ln2_b = (const float*)d_in[12];
    float* out = (float*)d_out;

    cudaFuncSetAttribute(gemm_tc2,             cudaFuncAttributeMaxDynamicSharedMemorySize, (int)GEMM_TC2_SMEM);
    cudaFuncSetAttribute(gemm_tc<true,false>,  cudaFuncAttributeMaxDynamicSharedMemorySize, (int)GEMM_TC_SMEM);
    cudaFuncSetAttribute(gemm_tc<false,false>, cudaFuncAttributeMaxDynamicSharedMemorySize, (int)GEMM_TC_SMEM);

    float* S = nullptr;
    cudaGetSymbolAddress((void**)&S, g_scratch);
    float* xqH  = S + OFF_XQH;
    float* xqL  = S + OFF_XQL;
    float* xkH  = S + OFF_XKH;
    float* xkL  = S + OFF_XKL;
    float* xvH  = S + OFF_XVH;
    float* xvL  = S + OFF_XVL;
    float* E    = S + OFF_E;
    float* atH  = S + OFF_ATH;
    float* atL  = S + OFF_ATL;
    float* Rt12 = S + OFF_RT12;
    float* h    = S + OFF_H;
    float* H1   = S + OFF_H1;
    float* P4   = S + OFF_P4;

    const float* xlast = x + (long)NB * CC * NN;

    // out[4:] = last (unchanged)
    cudaMemcpyAsync(out + (long)NB * CC * NN, xlast,
                    (size_t)12 * CC * NN * sizeof(float),
                    cudaMemcpyDeviceToDevice, 0);

    // xq (split out): 48 batches 64x1024x64, FFMA
    gemm_k<64,128,16,8,8,false,true,4,0><<<dim3(8,1,48),128>>>(
        Wq, xlast, xqH, 64, 64, NN, NN,
        (long)64*64, (long)64*NN, (long)64*NN, 4, 0,
        1.f, xqL);

    // xk (split out): 16 batches 64x1024x64, FFMA
    gemm_k<64,128,16,8,8,false,true,4,0><<<dim3(8,1,16),128>>>(
        Wk, x, xkH, 64, 64, NN, NN,
        (long)64*64, (long)64*NN, (long)64*NN, 4, 0,
        1.f, xkL);

    // xvT (split out): 4 batches 1024x256x256, TC (A=x K-major, B=Wv M-major)
    gemm_tc<true,false><<<dim3(2,8,4),256,GEMM_TC_SMEM>>>(
        x, Wv, xvH, CC, NN, CC, CC,
        (long)CC*NN, 0L, (long)NN*CC, 0, 0,
        1.f, bv, nullptr, 0, xvL);

    // energy: E[z][n][m] = sum_ch xq[z][ch][n]*xk[z%4][ch][m] (12 x 1024x1024x256, pre-split)
    gemm_tc2<<<dim3(8,8,12),256,GEMM_TC2_SMEM>>>(
        xqH, xqL, xkH, xkL, E, CC, NN, NN, NN,
        (long)CC*NN, (long)CC*NN, (long)NN*NN, 0, 4, 1.f);

    // softmax + split
    softmax_split_k<<<dim3(NN, NZ), 256>>>(E, atH, atL);

    // x_r: Rt12[z][m][c] = sum_k attn[z][k][m]*xvT[z%4][k][c] (12 x 1024x256x1024, pre-split)
    gemm_tc2<<<dim3(2,8,12),256,GEMM_TC2_SMEM>>>(
        atH, atL, xvH, xvL, Rt12, NN, NN, CC, CC,
        (long)NN*NN, (long)NN*CC, (long)NN*CC, 0, 4, 1.f);

    // LN1 (3-way mean * 1/48 + residual fused)
    ln1_k<<<TOK, 256>>>(x, Rt12, ln1_g, ln1_b, h);

    // MLP1: H1 = relu(h @ W1^T + b1)   (4096x1024x256, TC)
    gemm_tc<false,false><<<dim3(8,32,1),256,GEMM_TC_SMEM>>>(
        h, W1, H1, CC, CC, CC, 4*CC,
        0L, 0L, 0L, 0, 0,
        1.f, b1, nullptr, 1, nullptr);

    // MLP2 split-K (4 chunks of K=256)
    gemm_tc<false,false><<<dim3(2,32,4),256,GEMM_TC_SMEM>>>(
        H1, W2, P4, CC, 4*CC, 4*CC, CC,
        256L, 256L, (long)TOK*CC, 0, 0,
        1.f, nullptr, nullptr, 0, nullptr);

    // LN2 (split-K reduce + b2 + residual h fused) + relu + transpose into out[:4]
    ln2_out_k<<<TOK, 256>>>(P4, h, b2, ln2_g, ln2_b, out);
}

// round 17
// speedup vs baseline: 1.2107x; 1.0348x over previous
#include <cuda_runtime.h>
#include <math.h>
#include <stdint.h>

// Problem constants: x (16, 256, 1024); first = x[:4], last = x[4:]
static constexpr int CC   = 256;
static constexpr int NN   = 1024;
static constexpr int NB   = 4;      // first batches
static constexpr int NZ   = 12;     // (group-1)*b attention pairs
static constexpr int TOK  = NB * NN;

// Scratch layout (floats)
static constexpr long OFF_XQH  = 0;                        // 12*256*1024
static constexpr long OFF_XQL  = OFF_XQH + 3145728;
static constexpr long OFF_XKH  = OFF_XQL + 3145728;        // 4*256*1024
static constexpr long OFF_XKL  = OFF_XKH + 1048576;
static constexpr long OFF_XVT  = OFF_XKL + 1048576;        // 4*1024*256 raw
static constexpr long OFF_E    = OFF_XVT + 1048576;        // 12*1024*1024 (energy->attn)
static constexpr long OFF_RT12 = OFF_E   + 12582912;       // 12*1024*256
static constexpr long OFF_H    = OFF_RT12 + 3145728;       // 4096*256
static constexpr long OFF_H1   = OFF_H    + 1048576;       // 4096*1024
static constexpr long OFF_P4   = OFF_H1   + 4194304;       // 4*4096*256
static constexpr long SCRATCH_TOTAL = OFF_P4 + 4194304;    // ~138 MB

__device__ float g_scratch[SCRATCH_TOTAL];

// ===========================================================================
// tf32 split helpers + cp.async
// ===========================================================================
__device__ __forceinline__ float to_tf32(float v) {
    uint32_t u;
    asm("cvt.rna.tf32.f32 %0, %1;" : "=r"(u) : "f"(v));
    return __uint_as_float(u);
}
__device__ __forceinline__ void split_tf32(float v, float& hi, float& lo) {
    hi = to_tf32(v);
    lo = to_tf32(v - hi);
}
__device__ __forceinline__ void cp_async16(uint32_t s, const void* g) {
    asm volatile("cp.async.cg.shared.global [%0], [%1], 16;" :: "r"(s), "l"(g));
}
#define CP_COMMIT() asm volatile("cp.async.commit_group;")
#define CP_WAIT0()  asm volatile("cp.async.wait_group 0;")

#define MMA_TF32(d, a, b) \
    asm("mma.sync.aligned.m16n8k8.row.col.f32.tf32.tf32.f32 " \
        "{%0,%1,%2,%3}, {%4,%5,%6,%7}, {%8,%9}, {%0,%1,%2,%3};" \
        : "+f"((d)[0]), "+f"((d)[1]), "+f"((d)[2]), "+f"((d)[3]) \
        : "r"((a)[0]), "r"((a)[1]), "r"((a)[2]), "r"((a)[3]), \
          "r"((b)[0]), "r"((b)[1]))

// Shared compute step: 2 fm rows at a time, term-major -> dependent MMAs on
// the same accumulator are separated by 8 independent MMAs.
#define TILE_COMPUTE(AH, AL, BH, BL, SROW)                                        \
    _Pragma("unroll")                                                             \
    for (int ks = 0; ks < 16; ks += 8) {                                          \
        uint32_t bh[4][2], bl[4][2];                                              \
        _Pragma("unroll")                                                         \
        for (int fn = 0; fn < 4; fn++) {                                          \
            int n = wn + fn * 8 + g;                                              \
            bh[fn][0] = __float_as_uint((BH)[(ks + t    ) * (SROW) + n]);         \
            bh[fn][1] = __float_as_uint((BH)[(ks + t + 4) * (SROW) + n]);         \
            bl[fn][0] = __float_as_uint((BL)[(ks + t    ) * (SROW) + n]);         \
            bl[fn][1] = __float_as_uint((BL)[(ks + t + 4) * (SROW) + n]);         \
        }                                                                         \
        _Pragma("unroll")                                                         \
        for (int fmh = 0; fmh < 2; fmh++) {                                       \
            uint32_t ah[2][4], al[2][4];                                          \
            _Pragma("unroll")                                                     \
            for (int i = 0; i < 2; i++) {                                         \
                int m = wm + (fmh * 2 + i) * 16 + g;                              \
                ah[i][0] = __float_as_uint((AH)[(ks + t    ) * (SROW) + m]);      \
                ah[i][1] = __float_as_uint((AH)[(ks + t    ) * (SROW) + m + 8]);  \
                ah[i][2] = __float_as_uint((AH)[(ks + t + 4) * (SROW) + m]);      \
                ah[i][3] = __float_as_uint((AH)[(ks + t + 4) * (SROW) + m + 8]);  \
                al[i][0] = __float_as_uint((AL)[(ks + t    ) * (SROW) + m]);      \
                al[i][1] = __float_as_uint((AL)[(ks + t    ) * (SROW) + m + 8]);  \
                al[i][2] = __float_as_uint((AL)[(ks + t + 4) * (SROW) + m]);      \
                al[i][3] = __float_as_uint((AL)[(ks + t + 4) * (SROW) + m + 8]);  \
            }                                                                     \
            _Pragma("unroll")                                                     \
            for (int i = 0; i < 2; i++)                                           \
                _Pragma("unroll")                                                 \
                for (int fn = 0; fn < 4; fn++)                                    \
                    MMA_TF32(acc[fmh * 2 + i][fn], al[i], bh[fn]);                \
            _Pragma("unroll")                                                     \
            for (int i = 0; i < 2; i++)                                           \
                _Pragma("unroll")                                                 \
                for (int fn = 0; fn < 4; fn++)                                    \
                    MMA_TF32(acc[fmh * 2 + i][fn], ah[i], bl[fn]);                \
            _Pragma("unroll")                                                     \
            for (int i = 0; i < 2; i++)                                           \
                _Pragma("unroll")                                                 \
                for (int fn = 0; fn < 4; fn++)                                    \
                    MMA_TF32(acc[fmh * 2 + i][fn], ah[i], bh[fn]);                \
        }                                                                         \
    }

// ===========================================================================
// gemm_tc2: pre-split tf32x3 GEMM, both operands K-major, cp.async pipeline.
//   C[m][n] = alpha * sum_k A[k][m]*B[k][n], A/B given as hi/lo planes.
// 128x128x16 tiles, 8 warps (2m x 4n), 2 stages, 2 CTAs/SM.
// ===========================================================================
__global__ void __launch_bounds__(256, 2)
gemm_tc2(const float* __restrict__ Ahi, const float* __restrict__ Alo,
         const float* __restrict__ Bhi, const float* __restrict__ Blo,
         float* __restrict__ C, int K, int lda, int ldb, int ldc,
         long asb, long bsb, long csb, int aMod, int bMod, float alpha)
{
    constexpr int BM = 128, BN = 128, BK = 16;
    constexpr int SROW = BM + 8;          // 136
    constexpr int PLANE = BK * SROW;      // 2176 floats
    extern __shared__ float sm[];

    const int z = blockIdx.z;
    const long aoff = (long)(aMod ? (z % aMod) : z) * asb;
    const long boff = (long)(bMod ? (z % bMod) : z) * bsb;
    const float* pAh = Ahi + aoff; const float* pAl = Alo + aoff;
    const float* pBh = Bhi + boff; const float* pBl = Blo + boff;
    float* Cb = C + (long)z * csb;

    const int bm = blockIdx.y * BM;
    const int bn = blockIdx.x * BN;
    const int tid  = threadIdx.x;
    const int lane = tid & 31, warp = tid >> 5;
    const int g = lane >> 2, t = lane & 3;
    const int wm = (warp >> 2) * 64;
    const int wn = (warp & 3) * 32;

    float acc[4][4][4];
#pragma unroll
    for (int i = 0; i < 4; i++)
#pragma unroll
        for (int j = 0; j < 4; j++)
#pragma unroll
            for (int c = 0; c < 4; c++) acc[i][j][c] = 0.f;

    const uint32_t smbase = (uint32_t)__cvta_generic_to_shared(sm);

    auto issue = [&](int tt) {
        const int st = tt & 1;
        const int kt = tt * BK;
        const uint32_t base = smbase + (uint32_t)(st * 4 * PLANE) * 4u;
#pragma unroll
        for (int i = 0; i < 2; i++) {
            int v = tid + i * 256;
            int kk = v >> 5, c4 = (v & 31) << 2;
            uint32_t soff = (uint32_t)(kk * SROW + c4) * 4u;
            long ga = (long)(kt + kk) * lda + bm + c4;
            long gb = (long)(kt + kk) * ldb + bn + c4;
            cp_async16(base + 0u * PLANE * 4u + soff, pAh + ga);
            cp_async16(base + 1u * PLANE * 4u + soff, pAl + ga);
            cp_async16(base + 2u * PLANE * 4u + soff, pBh + gb);
            cp_async16(base + 3u * PLANE * 4u + soff, pBl + gb);
        }
        CP_COMMIT();
    };

    issue(0);
    const int ntiles = K / BK;
    for (int tt = 0; tt < ntiles; tt++) {
        CP_WAIT0();
        __syncthreads();
        if (tt + 1 < ntiles) issue(tt + 1);

        const int st = tt & 1;
        const float* AH = sm + st * 4 * PLANE;
        const float* AL = AH + PLANE;
        const float* BH = AL + PLANE;
        const float* BL = BH + PLANE;

        TILE_COMPUTE(AH, AL, BH, BL, SROW)
    }

#pragma unroll
    for (int fm = 0; fm < 4; fm++) {
        int r0 = bm + wm + fm * 16 + g;
        int r1 = r0 + 8;
#pragma unroll
        for (int fn = 0; fn < 4; fn++) {
            int cn = bn + wn + fn * 8 + 2 * t;
            *(float2*)(Cb + (long)r0 * ldc + cn) =
                make_float2(acc[fm][fn][0] * alpha, acc[fm][fn][1] * alpha);
            *(float2*)(Cb + (long)r1 * ldc + cn) =
                make_float2(acc[fm][fn][2] * alpha, acc[fm][fn][3] * alpha);
        }
    }
}

static constexpr size_t GEMM_TC2_SMEM = (size_t)(2 * 4 * 16 * 136) * sizeof(float); // 69632

// ===========================================================================
// gemm_tc: tf32x3 GEMM (split-on-store), double-buffered, 2 CTAs/SM.
// ===========================================================================
template<bool AKM, bool BKM>
__global__ void __launch_bounds__(256, 2)
gemm_tc(const float* __restrict__ A, const float* __restrict__ B, float* __restrict__ C,
        int K, int lda, int ldb, int ldc,
        long asb, long bsb, long csb, int aMod, int bMod,
        float alpha, const float* __restrict__ bias,
        const float* __restrict__ res, int relu)
{
    constexpr int BM = 128, BN = 128, BK = 16;
    constexpr int SROW = BM + 8;
    extern __shared__ float sm[];
    float* SA = sm;
    float* SB = sm + 2 * 2 * BK * SROW;

    const int z = blockIdx.z;
    const float* Ab = A + (long)(aMod ? (z % aMod) : z) * asb;
    const float* Bb = B + (long)(bMod ? (z % bMod) : z) * bsb;
    float* Cb = C + (long)z * csb;
    const float* Rb = res ? (res + (long)z * csb) : nullptr;

    const int bm = blockIdx.y * BM;
    const int bn = blockIdx.x * BN;
    const int tid  = threadIdx.x;
    const int lane = tid & 31, warp = tid >> 5;
    const int g = lane >> 2, t = lane & 3;
    const int wm = (warp >> 2) * 64;
    const int wn = (warp & 3) * 32;

    float acc[4][4][4];
#pragma unroll
    for (int i = 0; i < 4; i++)
#pragma unroll
        for (int j = 0; j < 4; j++)
#pragma unroll
            for (int c = 0; c < 4; c++) acc[i][j][c] = 0.f;

    float4 ra[2], rb[2];

    auto fetch = [&](int kt) {
#pragma unroll
        for (int i = 0; i < 2; i++) {
            int v = tid + i * 256;
            if (AKM) {
                int kk = v >> 5, mv = (v & 31) << 2;
                ra[i] = *(const float4*)(Ab + (long)(kt + kk) * lda + bm + mv);
            } else {
                int mm = v >> 2, kv = (v & 3) << 2;
                ra[i] = *(const float4*)(Ab + (long)(bm + mm) * lda + kt + kv);
            }
            if (BKM) {
                int kk = v >> 5, nv = (v & 31) << 2;
                rb[i] = *(const float4*)(Bb + (long)(kt + kk) * ldb + bn + nv);
            } else {
                int nn = v >> 2, kv = (v & 3) << 2;
                rb[i] = *(const float4*)(Bb + (long)(bn + nn) * ldb + kt + kv);
            }
        }
    };

    auto store = [&](int st) {
        float* AH = SA + (st * 2 + 0) * BK * SROW;
        float* AL = SA + (st * 2 + 1) * BK * SROW;
        float* BH = SB + (st * 2 + 0) * BK * SROW;
        float* BL = SB + (st * 2 + 1) * BK * SROW;
#pragma unroll
        for (int i = 0; i < 2; i++) {
            int v = tid + i * 256;
            if (AKM) {
                int kk = v >> 5, mv = (v & 31) << 2;
                float4 h4, l4;
                split_tf32(ra[i].x, h4.x, l4.x); split_tf32(ra[i].y, h4.y, l4.y);
                split_tf32(ra[i].z, h4.z, l4.z); split_tf32(ra[i].w, h4.w, l4.w);
                *(float4*)(AH + kk * SROW + mv) = h4;
                *(float4*)(AL + kk * SROW + mv) = l4;
            } else {
                int mm = v >> 2, kv = (v & 3) << 2;
                float h, l;
                split_tf32(ra[i].x, h, l); AH[(kv+0)*SROW+mm] = h; AL[(kv+0)*SROW+mm] = l;
                split_tf32(ra[i].y, h, l); AH[(kv+1)*SROW+mm] = h; AL[(kv+1)*SROW+mm] = l;
                split_tf32(ra[i].z, h, l); AH[(kv+2)*SROW+mm] = h; AL[(kv+2)*SROW+mm] = l;
                split_tf32(ra[i].w, h, l); AH[(kv+3)*SROW+mm] = h; AL[(kv+3)*SROW+mm] = l;
            }
            if (BKM) {
                int kk = v >> 5, nv = (v & 31) << 2;
                float4 h4, l4;
                split_tf32(rb[i].x, h4.x, l4.x); split_tf32(rb[i].y, h4.y, l4.y);
                split_tf32(rb[i].z, h4.z, l4.z); split_tf32(rb[i].w, h4.w, l4.w);
                *(float4*)(BH + kk * SROW + nv) = h4;
                *(float4*)(BL + kk * SROW + nv) = l4;
            } else {
                int nn = v >> 2, kv = (v & 3) << 2;
                float h, l;
                split_tf32(rb[i].x, h, l); BH[(kv+0)*SROW+nn] = h; BL[(kv+0)*SROW+nn] = l;
                split_tf32(rb[i].y, h, l); BH[(kv+1)*SROW+nn] = h; BL[(kv+1)*SROW+nn] = l;
                split_tf32(rb[i].z, h, l); BH[(kv+2)*SROW+nn] = h; BL[(kv+2)*SROW+nn] = l;
                split_tf32(rb[i].w, h, l); BH[(kv+3)*SROW+nn] = h; BL[(kv+3)*SROW+nn] = l;
            }
        }
    };

    fetch(0);
    store(0);
    __syncthreads();

    const int ntiles = K / BK;
    for (int tt = 0; tt < ntiles; tt++) {
        if (tt + 1 < ntiles) fetch((tt + 1) * BK);

        const int st = tt & 1;
        const float* AH = SA + (st * 2 + 0) * BK * SROW;
        const float* AL = SA + (st * 2 + 1) * BK * SROW;
        const float* BH = SB + (st * 2 + 0) * BK * SROW;
        const float* BL = SB + (st * 2 + 1) * BK * SROW;

        TILE_COMPUTE(AH, AL, BH, BL, SROW)

        if (tt + 1 < ntiles) {
            store((tt + 1) & 1);
            __syncthreads();
        }
    }

#pragma unroll
    for (int fm = 0; fm < 4; fm++) {
        int r0 = bm + wm + fm * 16 + g;
        int r1 = r0 + 8;
#pragma unroll
        for (int fn = 0; fn < 4; fn++) {
            int cn = bn + wn + fn * 8 + 2 * t;
            float v0 = acc[fm][fn][0] * alpha;
            float v1 = acc[fm][fn][1] * alpha;
            float v2 = acc[fm][fn][2] * alpha;
            float v3 = acc[fm][fn][3] * alpha;
            if (bias) { float b0 = bias[cn], b1x = bias[cn + 1];
                        v0 += b0; v1 += b1x; v2 += b0; v3 += b1x; }
            if (Rb)   { v0 += Rb[(long)r0 * ldc + cn];
                        v1 += Rb[(long)r0 * ldc + cn + 1];
                        v2 += Rb[(long)r1 * ldc + cn];
                        v3 += Rb[(long)r1 * ldc + cn + 1]; }
            if (relu) { v0 = fmaxf(v0, 0.f); v1 = fmaxf(v1, 0.f);
                        v2 = fmaxf(v2, 0.f); v3 = fmaxf(v3, 0.f); }
            *(float2*)(Cb + (long)r0 * ldc + cn) = make_float2(v0, v1);
            *(float2*)(Cb + (long)r1 * ldc + cn) = make_float2(v2, v3);
        }
    }
}

static constexpr size_t GEMM_TC_SMEM = (size_t)(2 * 2 * 16 * 136) * 2 * sizeof(float); // 69632

// ===========================================================================
// FFMA GEMM (small xq/xk convs); optional split output via Clo.
// ===========================================================================
template<int BM, int BN, int BK, int TM, int TN, bool AKM, bool BKM, int PA, int PB>
__global__ void __launch_bounds__((BM/TM)*(BN/TN))
gemm_k(const float* __restrict__ A, const float* __restrict__ B, float* __restrict__ C,
       int K, int lda, int ldb, int ldc,
       long asb, long bsb, long csb, int aMod, int bMod,
       float alpha, float* __restrict__ Clo)
{
    constexpr int NT = (BM/TM)*(BN/TN);
    const int z = blockIdx.z;
    const float* Ab = A + (aMod ? (long)(z % aMod) * asb : (long)z * asb);
    const float* Bb = B + (bMod ? (long)(z % bMod) * bsb : (long)z * bsb);
    float* Cb = C + (long)z * csb;
    float* CbL = Clo ? (Clo + (long)z * csb) : nullptr;

    const int bm = blockIdx.y * BM;
    const int bn = blockIdx.x * BN;

    __shared__ float As[BK][BM + PA];
    __shared__ float Bs[BK][BN + PB];

    const int tid = threadIdx.x;
    const int tx = tid % (BN / TN);
    const int ty = tid / (BN / TN);

    float acc[TM][TN];
#pragma unroll
    for (int i = 0; i < TM; i++)
#pragma unroll
        for (int j = 0; j < TN; j++) acc[i][j] = 0.f;

    for (int kt = 0; kt < K; kt += BK) {
        if (AKM) {
#pragma unroll
            for (int v = tid; v < BK * BM / 4; v += NT) {
                int kk = v / (BM / 4), mv = v % (BM / 4);
                float4 tv = *(const float4*)(Ab + (long)(kt + kk) * lda + bm + mv * 4);
                *(float4*)&As[kk][mv * 4] = tv;
            }
        } else {
#pragma unroll
            for (int v = tid; v < BK * BM / 4; v += NT) {
                int mm = v / (BK / 4), kv = v % (BK / 4);
                float4 tv = *(const float4*)(Ab + (long)(bm + mm) * lda + kt + kv * 4);
                As[kv * 4 + 0][mm] = tv.x;
                As[kv * 4 + 1][mm] = tv.y;
                As[kv * 4 + 2][mm] = tv.z;
                As[kv * 4 + 3][mm] = tv.w;
            }
        }
        if (BKM) {
#pragma unroll
            for (int v = tid; v < BK * BN / 4; v += NT) {
                int kk = v / (BN / 4), nv = v % (BN / 4);
                float4 tv = *(const float4*)(Bb + (long)(kt + kk) * ldb + bn + nv * 4);
                *(float4*)&Bs[kk][nv * 4] = tv;
            }
        } else {
#pragma unroll
            for (int v = tid; v < BK * BN / 4; v += NT) {
                int nn = v / (BK / 4), kv = v % (BK / 4);
                float4 tv = *(const float4*)(Bb + (long)(bn + nn) * ldb + kt + kv * 4);
                Bs[kv * 4 + 0][nn] = tv.x;
                Bs[kv * 4 + 1][nn] = tv.y;
                Bs[kv * 4 + 2][nn] = tv.z;
                Bs[kv * 4 + 3][nn] = tv.w;
            }
        }
        __syncthreads();

#pragma unroll
        for (int kk = 0; kk < BK; kk++) {
            float a[TM], bfr[TN];
            float4 a0 = *(const float4*)&As[kk][ty * TM];
            float4 a1 = *(const float4*)&As[kk][ty * TM + 4];
            a[0]=a0.x; a[1]=a0.y; a[2]=a0.z; a[3]=a0.w;
            a[4]=a1.x; a[5]=a1.y; a[6]=a1.z; a[7]=a1.w;
            float4 b0 = *(const float4*)&Bs[kk][tx * TN];
            float4 b1 = *(const float4*)&Bs[kk][tx * TN + 4];
            bfr[0]=b0.x; bfr[1]=b0.y; bfr[2]=b0.z; bfr[3]=b0.w;
            bfr[4]=b1.x; bfr[5]=b1.y; bfr[6]=b1.z; bfr[7]=b1.w;
#pragma unroll
            for (int i = 0; i < TM; i++)
#pragma unroll
                for (int j = 0; j < TN; j++)
                    acc[i][j] = fmaf(a[i], bfr[j], acc[i][j]);
        }
        __syncthreads();
    }

#pragma unroll
    for (int i = 0; i < TM; i++) {
        int cm = bm + ty * TM + i;
#pragma unroll
        for (int j = 0; j < TN; j++) {
            int cn = bn + tx * TN + j;
            float v = acc[i][j] * alpha;
            if (CbL) {
                float h, l;
                split_tf32(v, h, l);
                Cb[(long)cm * ldc + cn]  = h;
                CbL[(long)cm * ldc + cn] = l;
            } else {
                Cb[(long)cm * ldc + cn] = v;
            }
        }
    }
}

// ===========================================================================
// In-place row softmax over last dim of E[z][n][1024]
// ===========================================================================
__global__ void softmax_inplace_k(float* __restrict__ E)
{
    const int n = blockIdx.x;
    const int z = blockIdx.y;
    float* row = E + ((long)z * NN + n) * NN;
    const int tid = threadIdx.x;  // 256

    float e[4];
#pragma unroll
    for (int k = 0; k < 4; k++) e[k] = row[tid + 256 * k];

    __shared__ float red[256];
    float m = fmaxf(fmaxf(e[0], e[1]), fmaxf(e[2], e[3]));
    red[tid] = m; __syncthreads();
    for (int s = 128; s > 0; s >>= 1) {
        if (tid < s) red[tid] = fmaxf(red[tid], red[tid + s]);
        __syncthreads();
    }
    m = red[0]; __syncthreads();

    float ssum = 0.f;
#pragma unroll
    for (int k = 0; k < 4; k++) { e[k] = expf(e[k] - m); ssum += e[k]; }
    red[tid] = ssum; __syncthreads();
    for (int s = 128; s > 0; s >>= 1) {
        if (tid < s) red[tid] += red[tid + s];
        __syncthreads();
    }
    float inv = 1.f / red[0];
#pragma unroll
    for (int k = 0; k < 4; k++) row[tid + 256 * k] = e[k] * inv;
}

// ===========================================================================
// LN1 (fused 3-way mean of Rt12 + residual): h[t][c] = LN_c(x[b][c][n] + xr)
// ===========================================================================
__global__ void ln1_k(const float* __restrict__ x, const float* __restrict__ Rt12,
                      const float* __restrict__ gam, const float* __restrict__ bet,
                      float* __restrict__ h)
{
    const int t = blockIdx.x;
    const int b = t >> 10, n = t & 1023;
    const int c = threadIdx.x;
    long base = ((long)(3 * b) * NN + n) * CC + c;
    float r = Rt12[base] + Rt12[base + (long)NN * CC] + Rt12[base + 2L * NN * CC];
    float v = x[((long)b * CC + c) * NN + n] + r * (1.f / 48.f);

    __shared__ float red[256];
    red[c] = v; __syncthreads();
    for (int s = 128; s > 0; s >>= 1) { if (c < s) red[c] += red[c + s]; __syncthreads(); }
    float mu = red[0] * (1.f / CC); __syncthreads();
    float d = v - mu;
    red[c] = d * d; __syncthreads();
    for (int s = 128; s > 0; s >>= 1) { if (c < s) red[c] += red[c + s]; __syncthreads(); }
    float var = red[0] * (1.f / CC);
    h[(long)t * CC + c] = d * rsqrtf(var + 1e-6f) * gam[c] + bet[c];
}

// ===========================================================================
// LN2 (fused MLP2 split-K reduce + bias + residual) + relu + transposed write
// ===========================================================================
__global__ void ln2_out_k(const float* __restrict__ P4, const float* __restrict__ h,
                          const float* __restrict__ b2,
                          const float* __restrict__ gam, const float* __restrict__ bet,
                          float* __restrict__ out)
{
    const int t = blockIdx.x;
    const int b = t >> 10, n = t & 1023;
    const int c = threadIdx.x;
    long idx = (long)t * CC + c;
    float v = h[idx] + b2[c];
#pragma unroll
    for (int z = 0; z < 4; z++) v += P4[(long)z * TOK * CC + idx];

    __shared__ float red[256];
    red[c] = v; __syncthreads();
    for (int s = 128; s > 0; s >>= 1) { if (c < s) red[c] += red[c + s]; __syncthreads(); }
    float mu = red[0] * (1.f / CC); __syncthreads();
    float d = v - mu;
    red[c] = d * d; __syncthreads();
    for (int s = 128; s > 0; s >>= 1) { if (c < s) red[c] += red[c + s]; __syncthreads(); }
    float var = red[0] * (1.f / CC);
    float hv = d * rsqrtf(var + 1e-6f) * gam[c] + bet[c];
    out[((long)b * CC + c) * NN + n] = fmaxf(hv, 0.f);
}

// ===========================================================================
extern "C" void kernel_launch(void* const* d_in, const int* in_sizes, int n_in,
                              void* d_out, int out_size)
{
    (void)in_sizes; (void)n_in; (void)out_size;
    const float* x     = (const float*)d_in[0];
    const float* Wq    = (const float*)d_in[1];
    const float* Wk    = (const float*)d_in[2];
    const float* Wv    = (const float*)d_in[3];
    const float* bv    = (const float*)d_in[4];
    const float* ln1_g = (const float*)d_in[5];
    const float* ln1_b = (const float*)d_in[6];
    const float* W1    = (const float*)d_in[7];
    const float* b1    = (const float*)d_in[8];
    const float* W2    = (const float*)d_in[9];
    const float* b2    = (const float*)d_in[10];
    const float* ln2_g = (const float*)d_in[11];
    const float* ln2_b = (const float*)d_in[12];
    float* out = (float*)d_out;

    cudaFuncSetAttribute(gemm_tc2,             cudaFuncAttributeMaxDynamicSharedMemorySize, (int)GEMM_TC2_SMEM);
    cudaFuncSetAttribute(gemm_tc<true,true>,   cudaFuncAttributeMaxDynamicSharedMemorySize, (int)GEMM_TC_SMEM);
    cudaFuncSetAttribute(gemm_tc<true,false>,  cudaFuncAttributeMaxDynamicSharedMemorySize, (int)GEMM_TC_SMEM);
    cudaFuncSetAttribute(gemm_tc<false,false>, cudaFuncAttributeMaxDynamicSharedMemorySize, (int)GEMM_TC_SMEM);

    float* S = nullptr;
    cudaGetSymbolAddress((void**)&S, g_scratch);
    float* xqH  = S + OFF_XQH;
    float* xqL  = S + OFF_XQL;
    float* xkH  = S + OFF_XKH;
    float* xkL  = S + OFF_XKL;
    float* xvT  = S + OFF_XVT;
    float* E    = S + OFF_E;
    float* Rt12 = S + OFF_RT12;
    float* h    = S + OFF_H;
    float* H1   = S + OFF_H1;
    float* P4   = S + OFF_P4;

    const float* xlast = x + (long)NB * CC * NN;

    // out[4:] = last (unchanged)
    cudaMemcpyAsync(out + (long)NB * CC * NN, xlast,
                    (size_t)12 * CC * NN * sizeof(float),
                    cudaMemcpyDeviceToDevice, 0);

    // xq (split out): 48 batches 64x1024x64, FFMA
    gemm_k<64,128,16,8,8,false,true,4,0><<<dim3(8,1,48),128>>>(
        Wq, xlast, xqH, 64, 64, NN, NN,
        (long)64*64, (long)64*NN, (long)64*NN, 4, 0,
        1.f, xqL);

    // xk (split out): 16 batches 64x1024x64, FFMA
    gemm_k<64,128,16,8,8,false,true,4,0><<<dim3(8,1,16),128>>>(
        Wk, x, xkH, 64, 64, NN, NN,
        (long)64*64, (long)64*NN, (long)64*NN, 4, 0,
        1.f, xkL);

    // xvT raw: 4 batches 1024x256x256, TC (A=x K-major, B=Wv M-major)
    gemm_tc<true,false><<<dim3(2,8,4),256,GEMM_TC_SMEM>>>(
        x, Wv, xvT, CC, NN, CC, CC,
        (long)CC*NN, 0L, (long)NN*CC, 0, 0,
        1.f, bv, nullptr, 0);

    // energy: E[z][n][m] = sum_ch xq[z][ch][n]*xk[z%4][ch][m] (12 x 1024x1024x256, pre-split)
    gemm_tc2<<<dim3(8,8,12),256,GEMM_TC2_SMEM>>>(
        xqH, xqL, xkH, xkL, E, CC, NN, NN, NN,
        (long)CC*NN, (long)CC*NN, (long)NN*NN, 0, 4, 1.f);

    // softmax rows in place
    softmax_inplace_k<<<dim3(NN, NZ), 256>>>(E);

    // x_r: Rt12[z][m][c] = sum_k attn[z][k][m]*xvT[z%4][k][c] (12 x 1024x256x1024, TC)
    gemm_tc<true,true><<<dim3(2,8,12),256,GEMM_TC_SMEM>>>(
        E, xvT, Rt12, NN, NN, CC, CC,
        (long)NN*NN, (long)NN*CC, (long)NN*CC, 0, 4,
        1.f, nullptr, nullptr, 0);

    // LN1 (3-way mean * 1/48 + residual fused)
    ln1_k<<<TOK, 256>>>(x, Rt12, ln1_g, ln1_b, h);

    // MLP1: H1 = relu(h @ W1^T + b1)   (4096x1024x256, TC)
    gemm_tc<false,false><<<dim3(8,32,1),256,GEMM_TC_SMEM>>>(
        h, W1, H1, CC, CC, CC, 4*CC,
        0L, 0L, 0L, 0, 0,
        1.f, b1, nullptr, 1);

    // MLP2 split-K (4 chunks of K=256)
    gemm_tc<false,false><<<dim3(2,32,4),256,GEMM_TC_SMEM>>>(
        H1, W2, P4, CC, 4*CC, 4*CC, CC,
        256L, 256L, (long)TOK*CC, 0, 0,
        1.f, nullptr, nullptr, 0);

    // LN2 (split-K reduce + b2 + residual h fused) + relu + transpose into out[:4]
    ln2_out_k<<<TOK, 256>>>(P4, h, b2, ln2_g, ln2_b, out);
}